// round 1
// baseline (speedup 1.0000x reference)
#include <cuda_runtime.h>
#include <cuda_bf16.h>
#include <math.h>

// inputs (metadata order): x[f32 N_NODES*128] (unused), src[i32 E], dst[i32 E],
// path_len[i32 E], b[f32 5]. output: f32 N_NODES*N_NODES.
//
// Semantics: out = zeros; out[src[i], dst[i]] = b[min(path_len[i],5)-1], with
// LAST duplicate (highest i) winning. Implemented deterministically via
// atomicMax of packed key ((i+1)<<3 | idx) followed by a decode sweep.

#ifndef MAX_PATH_DISTANCE
#define MAX_PATH_DISTANCE 5
#endif

__device__ __forceinline__ int pack_key(int pair_idx, int plen) {
    int idx = min(plen, MAX_PATH_DISTANCE) - 1;   // 0..4
    return ((pair_idx + 1) << 3) | idx;           // always > 0
}

__global__ void scatter_max_kernel(const int* __restrict__ src,
                                   const int* __restrict__ dst,
                                   const int* __restrict__ plen,
                                   int* __restrict__ out_i,
                                   int n_pairs, int n_nodes) {
    int t = blockIdx.x * blockDim.x + threadIdx.x;
    int base = t * 4;
    if (base >= n_pairs) return;

    if (base + 3 < n_pairs) {
        int4 s = *reinterpret_cast<const int4*>(src + base);
        int4 d = *reinterpret_cast<const int4*>(dst + base);
        int4 p = *reinterpret_cast<const int4*>(plen + base);

        long long p0 = (long long)s.x * n_nodes + d.x;
        long long p1 = (long long)s.y * n_nodes + d.y;
        long long p2 = (long long)s.z * n_nodes + d.z;
        long long p3 = (long long)s.w * n_nodes + d.w;

        atomicMax(out_i + p0, pack_key(base + 0, p.x));
        atomicMax(out_i + p1, pack_key(base + 1, p.y));
        atomicMax(out_i + p2, pack_key(base + 2, p.z));
        atomicMax(out_i + p3, pack_key(base + 3, p.w));
    } else {
        for (int k = base; k < n_pairs; ++k) {
            long long pos = (long long)src[k] * n_nodes + dst[k];
            atomicMax(out_i + pos, pack_key(k, plen[k]));
        }
    }
}

__global__ void decode_kernel(int* __restrict__ out_i,
                              const float* __restrict__ b,
                              int total4) {
    int i = blockIdx.x * blockDim.x + threadIdx.x;
    if (i >= total4) return;
    int4 v = reinterpret_cast<int4*>(out_i)[i];
    float4 r;
    r.x = v.x ? __ldg(&b[v.x & 7]) : 0.0f;
    r.y = v.y ? __ldg(&b[v.y & 7]) : 0.0f;
    r.z = v.z ? __ldg(&b[v.z & 7]) : 0.0f;
    r.w = v.w ? __ldg(&b[v.w & 7]) : 0.0f;
    reinterpret_cast<float4*>(out_i)[i] = r;
}

extern "C" void kernel_launch(void* const* d_in, const int* in_sizes, int n_in,
                              void* d_out, int out_size) {
    const int* src  = (const int*)d_in[1];
    const int* dst  = (const int*)d_in[2];
    const int* plen = (const int*)d_in[3];
    const float* b  = (const float*)d_in[4];

    int n_pairs = in_sizes[1];
    // out is n_nodes x n_nodes
    int n_nodes = (int)llround(sqrt((double)out_size));

    int* out_i = (int*)d_out;

    // 1) zero baseline (required each replay: leftover float bits from the
    //    previous replay compare greater-than any packed key as signed int)
    cudaMemsetAsync(d_out, 0, (size_t)out_size * sizeof(float));

    // 2) deterministic last-write-wins scatter via packed atomicMax
    {
        int threads = 256;
        int work = (n_pairs + 3) / 4;
        int blocks = (work + threads - 1) / threads;
        scatter_max_kernel<<<blocks, threads>>>(src, dst, plen, out_i,
                                                n_pairs, n_nodes);
    }

    // 3) decode packed keys -> b values, untouched cells -> 0.0f
    {
        int total4 = out_size / 4;
        int threads = 256;
        int blocks = (total4 + threads - 1) / threads;
        decode_kernel<<<blocks, threads>>>(out_i, b, total4);
    }
}